// round 3
// baseline (speedup 1.0000x reference)
#include <cuda_runtime.h>
#include <cstdint>
#include <cstddef>

#define BB 1024
#define SS 1024
#define FF 36
#define HH 20

// Scratch: encoder final hidden state (tanh'd), and onehot dtype flag.
__device__ float g_h[BB * HH];
__device__ int g_oh64;

// ---------------------------------------------------------------------------
// Fast activations (EX2-based). Abs error ~1e-6, safe vs 1e-3 rel-err.
// ---------------------------------------------------------------------------
__device__ __forceinline__ float sigm_fast(float v) {
    float a = fminf(-v, 80.f);
    return __fdividef(1.f, 1.f + __expf(a));
}
__device__ __forceinline__ float tanh_fast(float v) {
    float a = fminf(2.f * v, 80.f);
    float e = __expf(a);
    return __fdividef(e - 1.f, e + 1.f);
}

// ---------------------------------------------------------------------------
// Detect int64 vs int32 onehots: int64 little-endian => odd int32 words all 0.
// ---------------------------------------------------------------------------
__global__ void detect_kernel(const int* __restrict__ oh) {
    if (threadIdx.x == 0 && blockIdx.x == 0) {
        int z = 1;
        for (int i = 1; i < 64; i += 2)
            if (oh[i] != 0) { z = 0; break; }
        g_oh64 = z;
    }
}

// ---------------------------------------------------------------------------
// Embedding + concat -> origin. One thread per (b,s) row: 9 float4 stores.
// ---------------------------------------------------------------------------
__global__ void embed_kernel(const float* __restrict__ x,
                             const int* __restrict__ oh,
                             const float* __restrict__ e0,
                             const float* __restrict__ e1,
                             const float* __restrict__ e2,
                             const float* __restrict__ e3,
                             float* __restrict__ origin) {
    int idx = blockIdx.x * blockDim.x + threadIdx.x;
    if (idx >= BB * SS) return;
    int i0, i1, i2, i3;
    if (g_oh64) {
        const int* p = oh + (size_t)idx * 8;
        i0 = p[0]; i1 = p[2]; i2 = p[4]; i3 = p[6];
    } else {
        int4 o = reinterpret_cast<const int4*>(oh)[idx];
        i0 = o.x; i1 = o.y; i2 = o.z; i3 = o.w;
    }
    const float4* xr = reinterpret_cast<const float4*>(x + (size_t)idx * 12);
    float4* out = reinterpret_cast<float4*>(origin + (size_t)idx * FF);
    out[0] = xr[0];
    out[1] = xr[1];
    out[2] = xr[2];
    out[3] = reinterpret_cast<const float4*>(e0)[i0];
    out[4] = reinterpret_cast<const float4*>(e1)[i1];
    const float4* e2p = reinterpret_cast<const float4*>(e2);
    out[5] = e2p[i2 * 2];
    out[6] = e2p[i2 * 2 + 1];
    const float4* e3p = reinterpret_cast<const float4*>(e3);
    out[7] = e3p[i3 * 2];
    out[8] = e3p[i3 * 2 + 1];
}

// ---------------------------------------------------------------------------
// Encoder GRU. 20 threads per batch element (thread k = hidden unit k),
// 8 batches per 160-thread block, 128 persistent blocks.
// Weights for rows k, 20+k, 40+k live in registers; activations broadcast
// from shared (1 LDS feeds 3 FFMAs -> FFMA-pipe bound).
// ---------------------------------------------------------------------------
__global__ void __launch_bounds__(160, 1) encoder_kernel(
    const float* __restrict__ xin,
    const float* __restrict__ Wih, const float* __restrict__ Whh,
    const float* __restrict__ bih, const float* __restrict__ bhh) {
    __shared__ float h_sh[8][HH];
    __shared__ float x_sh[8][FF];

    int tid = threadIdx.x;
    int bl = tid / HH;   // 0..7
    int k = tid % HH;    // 0..19
    int b = blockIdx.x * 8 + bl;

    float wr[FF], wz[FF], wn[FF];
#pragma unroll
    for (int f = 0; f < FF; f++) {
        wr[f] = Wih[k * FF + f];
        wz[f] = Wih[(20 + k) * FF + f];
        wn[f] = Wih[(40 + k) * FF + f];
    }
    float ur[HH], uz[HH], un[HH];
#pragma unroll
    for (int j = 0; j < HH; j++) {
        ur[j] = Whh[k * HH + j];
        uz[j] = Whh[(20 + k) * HH + j];
        un[j] = Whh[(40 + k) * HH + j];
    }
    float br = bih[k] + bhh[k];
    float bz = bih[20 + k] + bhh[20 + k];
    float bin_ = bih[40 + k];
    float bhn = bhh[40 + k];

    h_sh[bl][k] = 0.f;
    float hcur = 0.f;

    const float* xrow = xin + (size_t)b * SS * FF;
    float px0 = xrow[k];
    float px1 = (k < 16) ? xrow[20 + k] : 0.f;

    for (int s = 0; s < SS; ++s) {
        x_sh[bl][k] = px0;
        if (k < 16) x_sh[bl][20 + k] = px1;
        __syncthreads();
        if (s + 1 < SS) {
            px0 = xrow[(size_t)(s + 1) * FF + k];
            px1 = (k < 16) ? xrow[(size_t)(s + 1) * FF + 20 + k] : 0.f;
        }
        float gr = br, gz = bz, gin = bin_, ghn = bhn;
#pragma unroll
        for (int f = 0; f < FF; ++f) {
            float xv = x_sh[bl][f];
            gr = fmaf(wr[f], xv, gr);
            gz = fmaf(wz[f], xv, gz);
            gin = fmaf(wn[f], xv, gin);
        }
#pragma unroll
        for (int j = 0; j < HH; ++j) {
            float hv = h_sh[bl][j];
            gr = fmaf(ur[j], hv, gr);
            gz = fmaf(uz[j], hv, gz);
            ghn = fmaf(un[j], hv, ghn);
        }
        float r = sigm_fast(gr);
        float z = sigm_fast(gz);
        float n = tanh_fast(fmaf(r, ghn, gin));
        float hnew = fmaf(z, hcur - n, n);  // (1-z)*n + z*h
        __syncthreads();
        h_sh[bl][k] = hnew;
        hcur = hnew;
    }
    g_h[b * HH + k] = tanh_fast(hcur);
}

// ---------------------------------------------------------------------------
// Decoder: autoregressive GRU (tanh-wrapped) + Wfc projection each step.
// Same thread mapping. Wfc in shared (stride-21 padded, conflict-free).
// Writes xs time-flipped.
// ---------------------------------------------------------------------------
__global__ void __launch_bounds__(160, 1) decoder_kernel(
    const float* __restrict__ Wih, const float* __restrict__ Whh,
    const float* __restrict__ bih, const float* __restrict__ bhh,
    const float* __restrict__ Wfc, const float* __restrict__ bfc,
    float* __restrict__ out_xs) {
    __shared__ float h_sh[8][HH];
    __shared__ float x_sh[8][FF];
    __shared__ float wfc_sh[FF * 21];
    __shared__ float bfc_sh[FF];

    int tid = threadIdx.x;
    int bl = tid / HH;
    int k = tid % HH;
    int b = blockIdx.x * 8 + bl;

    float wr[FF], wz[FF], wn[FF];
#pragma unroll
    for (int f = 0; f < FF; f++) {
        wr[f] = Wih[k * FF + f];
        wz[f] = Wih[(20 + k) * FF + f];
        wn[f] = Wih[(40 + k) * FF + f];
    }
    float ur[HH], uz[HH], un[HH];
#pragma unroll
    for (int j = 0; j < HH; j++) {
        ur[j] = Whh[k * HH + j];
        uz[j] = Whh[(20 + k) * HH + j];
        un[j] = Whh[(40 + k) * HH + j];
    }
    float br = bih[k] + bhh[k];
    float bz = bih[20 + k] + bhh[20 + k];
    float bin_ = bih[40 + k];
    float bhn = bhh[40 + k];

    for (int i = tid; i < FF * HH; i += 160) {
        int f = i / HH, j = i % HH;
        wfc_sh[f * 21 + j] = Wfc[i];
    }
    if (tid < FF) bfc_sh[tid] = bfc[tid];

    float hcur = g_h[b * HH + k];
    h_sh[bl][k] = hcur;
    __syncthreads();

    float* orow = out_xs + (size_t)b * SS * FF;

    // x0 = tanh(h @ Wfc^T + bfc) -> goes to flipped position S-1
    {
        float xa = bfc_sh[k];
        float xb = (k < 16) ? bfc_sh[20 + k] : 0.f;
#pragma unroll
        for (int j = 0; j < HH; ++j) {
            float hv = h_sh[bl][j];
            xa = fmaf(wfc_sh[k * 21 + j], hv, xa);
            if (k < 16) xb = fmaf(wfc_sh[(20 + k) * 21 + j], hv, xb);
        }
        xa = tanh_fast(xa);
        orow[(size_t)(SS - 1) * FF + k] = xa;
        x_sh[bl][k] = xa;
        if (k < 16) {
            xb = tanh_fast(xb);
            orow[(size_t)(SS - 1) * FF + 20 + k] = xb;
            x_sh[bl][20 + k] = xb;
        }
    }
    __syncthreads();

    for (int st = 1; st < SS; ++st) {
        // GRU cell on (x_prev, h_prev), then tanh
        float gr = br, gz = bz, gin = bin_, ghn = bhn;
#pragma unroll
        for (int f = 0; f < FF; ++f) {
            float xv = x_sh[bl][f];
            gr = fmaf(wr[f], xv, gr);
            gz = fmaf(wz[f], xv, gz);
            gin = fmaf(wn[f], xv, gin);
        }
#pragma unroll
        for (int j = 0; j < HH; ++j) {
            float hv = h_sh[bl][j];
            gr = fmaf(ur[j], hv, gr);
            gz = fmaf(uz[j], hv, gz);
            ghn = fmaf(un[j], hv, ghn);
        }
        float r = sigm_fast(gr);
        float z = sigm_fast(gz);
        float n = tanh_fast(fmaf(r, ghn, gin));
        float hnew = tanh_fast(fmaf(z, hcur - n, n));
        __syncthreads();
        h_sh[bl][k] = hnew;
        hcur = hnew;
        __syncthreads();

        // xnew = tanh(hnew @ Wfc^T + bfc), write flipped
        float xa = bfc_sh[k];
        float xb = (k < 16) ? bfc_sh[20 + k] : 0.f;
#pragma unroll
        for (int j = 0; j < HH; ++j) {
            float hv = h_sh[bl][j];
            xa = fmaf(wfc_sh[k * 21 + j], hv, xa);
            if (k < 16) xb = fmaf(wfc_sh[(20 + k) * 21 + j], hv, xb);
        }
        xa = tanh_fast(xa);
        int so = SS - 1 - st;
        orow[(size_t)so * FF + k] = xa;
        x_sh[bl][k] = xa;
        if (k < 16) {
            xb = tanh_fast(xb);
            orow[(size_t)so * FF + 20 + k] = xb;
            x_sh[bl][20 + k] = xb;
        }
        __syncthreads();
    }
}

// ---------------------------------------------------------------------------
// Launch
// ---------------------------------------------------------------------------
extern "C" void kernel_launch(void* const* d_in, const int* in_sizes, int n_in,
                              void* d_out, int out_size) {
    const float* x = (const float*)d_in[0];
    const int* oh = (const int*)d_in[1];
    const float* e0 = (const float*)d_in[2];
    const float* e1 = (const float*)d_in[3];
    const float* e2 = (const float*)d_in[4];
    const float* e3 = (const float*)d_in[5];
    const float* Wih1 = (const float*)d_in[6];
    const float* Whh1 = (const float*)d_in[7];
    const float* bih1 = (const float*)d_in[8];
    const float* bhh1 = (const float*)d_in[9];
    const float* Wih2 = (const float*)d_in[10];
    const float* Whh2 = (const float*)d_in[11];
    const float* bih2 = (const float*)d_in[12];
    const float* bhh2 = (const float*)d_in[13];
    const float* Wfc = (const float*)d_in[14];
    const float* bfc = (const float*)d_in[15];

    float* out = (float*)d_out;
    float* origin = out;                          // (B,S,F)
    float* xs = out + (size_t)BB * SS * FF;       // (B,S,F) flipped decode

    detect_kernel<<<1, 32>>>(oh);
    embed_kernel<<<(BB * SS + 255) / 256, 256>>>(x, oh, e0, e1, e2, e3, origin);
    encoder_kernel<<<BB / 8, 160>>>(origin, Wih1, Whh1, bih1, bhh1);
    decoder_kernel<<<BB / 8, 160>>>(Wih2, Whh2, bih2, bhh2, Wfc, bfc, xs);
}

// round 4
// speedup vs baseline: 1.0544x; 1.0544x over previous
#include <cuda_runtime.h>
#include <cstdint>
#include <cstddef>

#define BB 1024
#define SS 1024
#define FF 36
#define HH 20

typedef unsigned long long ull;

// Scratch: encoder final hidden state (tanh'd), packed per batch-pair.
__device__ ull g_h2[(BB / 2) * HH];
__device__ int g_oh64;

// ---------------------------------------------------------------------------
// f32x2 packed helpers
// ---------------------------------------------------------------------------
__device__ __forceinline__ ull pk2(float a, float b) {
    ull r; asm("mov.b64 %0,{%1,%2};" : "=l"(r) : "f"(a), "f"(b)); return r;
}
__device__ __forceinline__ void upk2(ull v, float& a, float& b) {
    asm("mov.b64 {%0,%1},%2;" : "=f"(a), "=f"(b) : "l"(v));
}
__device__ __forceinline__ ull fma2(ull a, ull b, ull c) {
    ull d; asm("fma.rn.f32x2 %0,%1,%2,%3;" : "=l"(d) : "l"(a), "l"(b), "l"(c)); return d;
}
__device__ __forceinline__ ull add2(ull a, ull b) {
    ull d; asm("add.rn.f32x2 %0,%1,%2;" : "=l"(d) : "l"(a), "l"(b)); return d;
}

// ---------------------------------------------------------------------------
// Fast activations (EX2-based). Abs error ~1e-6, safe vs 1e-3 rel-err.
// ---------------------------------------------------------------------------
__device__ __forceinline__ float sigm_fast(float v) {
    float a = fminf(-v, 80.f);
    return __fdividef(1.f, 1.f + __expf(a));
}
__device__ __forceinline__ float tanh_fast(float v) {
    float a = fminf(2.f * v, 80.f);
    float e = __expf(a);
    return __fdividef(e - 1.f, e + 1.f);
}

// ---------------------------------------------------------------------------
// Detect int64 vs int32 onehots.
// ---------------------------------------------------------------------------
__global__ void detect_kernel(const int* __restrict__ oh) {
    if (threadIdx.x == 0 && blockIdx.x == 0) {
        int z = 1;
        for (int i = 1; i < 64; i += 2)
            if (oh[i] != 0) { z = 0; break; }
        g_oh64 = z;
    }
}

// ---------------------------------------------------------------------------
// Embedding + concat -> origin.
// ---------------------------------------------------------------------------
__global__ void embed_kernel(const float* __restrict__ x,
                             const int* __restrict__ oh,
                             const float* __restrict__ e0,
                             const float* __restrict__ e1,
                             const float* __restrict__ e2,
                             const float* __restrict__ e3,
                             float* __restrict__ origin) {
    int idx = blockIdx.x * blockDim.x + threadIdx.x;
    if (idx >= BB * SS) return;
    int i0, i1, i2, i3;
    if (g_oh64) {
        const int* p = oh + (size_t)idx * 8;
        i0 = p[0]; i1 = p[2]; i2 = p[4]; i3 = p[6];
    } else {
        int4 o = reinterpret_cast<const int4*>(oh)[idx];
        i0 = o.x; i1 = o.y; i2 = o.z; i3 = o.w;
    }
    const float4* xr = reinterpret_cast<const float4*>(x + (size_t)idx * 12);
    float4* out = reinterpret_cast<float4*>(origin + (size_t)idx * FF);
    out[0] = xr[0];
    out[1] = xr[1];
    out[2] = xr[2];
    out[3] = reinterpret_cast<const float4*>(e0)[i0];
    out[4] = reinterpret_cast<const float4*>(e1)[i1];
    const float4* e2p = reinterpret_cast<const float4*>(e2);
    out[5] = e2p[i2 * 2];
    out[6] = e2p[i2 * 2 + 1];
    const float4* e3p = reinterpret_cast<const float4*>(e3);
    out[7] = e3p[i3 * 2];
    out[8] = e3p[i3 * 2 + 1];
}

// ---------------------------------------------------------------------------
// Encoder GRU, f32x2 packed over batch pairs.
// Block: 160 threads = 4 pairs x 40 threads. Thread = (unit k, half).
// Each thread does half the dot products for all 3 gates of unit k for a
// packed pair of batches; halves combined with one shfl.xor(1).
// Single barrier per step via double-buffered x/h tiles.
// ---------------------------------------------------------------------------
__global__ void __launch_bounds__(160, 1) encoder_kernel(
    const float* __restrict__ xin,
    const float* __restrict__ Wih, const float* __restrict__ Whh,
    const float* __restrict__ bih, const float* __restrict__ bhh) {
    __shared__ ull x2s[2][4][FF];
    __shared__ ull h2s[2][4][HH];

    int tid = threadIdx.x;
    int pair = tid / 40;
    int l = tid % 40;       // 0..39
    int k = l >> 1;         // unit 0..19
    int half = l & 1;       // K-half
    int gp = blockIdx.x * 4 + pair;          // global pair index
    int b0 = gp * 2;
    int b1 = b0 + 1;

    // Packed weights for this (k, half): 3 gates x 18 input cols, 3 x 10 hidden cols
    ull wih[3][18], whh[3][10];
#pragma unroll
    for (int g = 0; g < 3; g++) {
        int row = g * HH + k;
#pragma unroll
        for (int f = 0; f < 18; f++) {
            float w = Wih[row * FF + half * 18 + f];
            wih[g][f] = pk2(w, w);
        }
#pragma unroll
        for (int j = 0; j < 10; j++) {
            float w = Whh[row * HH + half * 10 + j];
            whh[g][j] = pk2(w, w);
        }
    }
    float br = bih[k] + bhh[k];
    float bz = bih[HH + k] + bhh[HH + k];
    float bin_ = bih[2 * HH + k];
    float bhn = bhh[2 * HH + k];

    const float* xr0 = xin + (size_t)b0 * SS * FF;
    const float* xr1 = xin + (size_t)b1 * SS * FF;

    // x(0) into buffer 0, prefetch x(1) into regs
    float pa = 0.f, pb = 0.f;
    if (l < FF) {
        x2s[0][pair][l] = pk2(xr0[l], xr1[l]);
        pa = xr0[FF + l];
        pb = xr1[FF + l];
    }
    if (half == 0) h2s[0][pair][k] = 0ULL;
    __syncthreads();

    float hlo = 0.f, hhi = 0.f;

    for (int s = 0; s < SS; ++s) {
        int cur = s & 1, nxt = cur ^ 1;
        ull ar = 0, az = 0, ain = 0, ahn = 0;
        const ull* xv = x2s[cur][pair] + half * 18;
        const ull* hv = h2s[cur][pair] + half * 10;
#pragma unroll
        for (int f = 0; f < 18; ++f) {
            ull v = xv[f];
            ar = fma2(wih[0][f], v, ar);
            az = fma2(wih[1][f], v, az);
            ain = fma2(wih[2][f], v, ain);
        }
#pragma unroll
        for (int j = 0; j < 10; ++j) {
            ull v = hv[j];
            ar = fma2(whh[0][j], v, ar);
            az = fma2(whh[1][j], v, az);
            ahn = fma2(whh[2][j], v, ahn);
        }
        // combine halves (partner = lane xor 1, always same warp)
        ar = add2(ar, __shfl_xor_sync(0xffffffffu, ar, 1));
        az = add2(az, __shfl_xor_sync(0xffffffffu, az, 1));
        ain = add2(ain, __shfl_xor_sync(0xffffffffu, ain, 1));
        ahn = add2(ahn, __shfl_xor_sync(0xffffffffu, ahn, 1));

        float rl, rh, zl, zh, il, ih, nl, nh;
        upk2(ar, rl, rh); upk2(az, zl, zh); upk2(ain, il, ih); upk2(ahn, nl, nh);
        float r0 = sigm_fast(rl + br), r1 = sigm_fast(rh + br);
        float z0 = sigm_fast(zl + bz), z1 = sigm_fast(zh + bz);
        float n0 = tanh_fast(il + bin_ + r0 * (nl + bhn));
        float n1 = tanh_fast(ih + bin_ + r1 * (nh + bhn));
        hlo = fmaf(z0, hlo - n0, n0);
        hhi = fmaf(z1, hhi - n1, n1);

        if (s + 1 < SS) {
            if (half == 0) h2s[nxt][pair][k] = pk2(hlo, hhi);
            if (l < FF) {
                x2s[nxt][pair][l] = pk2(pa, pb);
                if (s + 2 < SS) {
                    pa = xr0[(size_t)(s + 2) * FF + l];
                    pb = xr1[(size_t)(s + 2) * FF + l];
                }
            }
        }
        __syncthreads();
    }

    if (half == 0)
        g_h2[gp * HH + k] = pk2(tanh_fast(hlo), tanh_fast(hhi));
}

// ---------------------------------------------------------------------------
// Decoder: autoregressive tanh-GRU + Wfc projection, f32x2 packed.
// Same (k, half) mapping. Wih2/Wfc rows in regs; Whh2 packed in shared
// (per-thread lanes, 2-way max conflict). Two barriers per step.
// ---------------------------------------------------------------------------
__global__ void __launch_bounds__(160, 1) decoder_kernel(
    const float* __restrict__ Wih, const float* __restrict__ Whh,
    const float* __restrict__ bih, const float* __restrict__ bhh,
    const float* __restrict__ Wfc, const float* __restrict__ bfc,
    float* __restrict__ out_xs) {
    __shared__ ull x2s[2][4][FF];
    __shared__ ull h2s[2][4][HH];
    __shared__ ull whh_sh[3][10][40];

    int tid = threadIdx.x;
    int pair = tid / 40;
    int l = tid % 40;
    int k = l >> 1;
    int half = l & 1;
    int gp = blockIdx.x * 4 + pair;
    int b0 = gp * 2;
    int b1 = b0 + 1;

    ull wih[3][18];
#pragma unroll
    for (int g = 0; g < 3; g++) {
        int row = g * HH + k;
#pragma unroll
        for (int f = 0; f < 18; f++) {
            float w = Wih[row * FF + half * 18 + f];
            wih[g][f] = pk2(w, w);
        }
    }
    if (tid < 40) {
        int kk = tid >> 1, hh = tid & 1;
#pragma unroll
        for (int g = 0; g < 3; g++)
#pragma unroll
            for (int j = 0; j < 10; j++) {
                float w = Whh[(g * HH + kk) * HH + hh * 10 + j];
                whh_sh[g][j][tid] = pk2(w, w);
            }
    }
    // Wfc row for this thread's projection output feature f = l (l < 36)
    ull wfc_pk[HH];
    ull bfc2 = 0ULL;
    if (l < FF) {
#pragma unroll
        for (int j = 0; j < HH; j++) {
            float w = Wfc[l * HH + j];
            wfc_pk[j] = pk2(w, w);
        }
        float bv = bfc[l];
        bfc2 = pk2(bv, bv);
    }
    float br = bih[k] + bhh[k];
    float bz = bih[HH + k] + bhh[HH + k];
    float bin_ = bih[2 * HH + k];
    float bhn = bhh[2 * HH + k];

    // initial hidden state (tanh'd encoder output)
    ull h0p = g_h2[gp * HH + k];
    float hlo, hhi;
    upk2(h0p, hlo, hhi);
    if (half == 0) h2s[0][pair][k] = h0p;
    __syncthreads();

    float* orow0 = out_xs + (size_t)b0 * SS * FF;
    float* orow1 = out_xs + (size_t)b1 * SS * FF;

    // x0 = tanh(h @ Wfc^T + bfc) -> flipped position S-1
    if (l < FF) {
        ull acc = bfc2;
#pragma unroll
        for (int j = 0; j < HH; ++j)
            acc = fma2(wfc_pk[j], h2s[0][pair][j], acc);
        float xa, xb;
        upk2(acc, xa, xb);
        xa = tanh_fast(xa);
        xb = tanh_fast(xb);
        orow0[(size_t)(SS - 1) * FF + l] = xa;
        orow1[(size_t)(SS - 1) * FF + l] = xb;
        x2s[0][pair][l] = pk2(xa, xb);
    }
    __syncthreads();

    int cur = 0;
    for (int st = 1; st < SS; ++st) {
        int nxt = cur ^ 1;
        ull ar = 0, az = 0, ain = 0, ahn = 0;
        const ull* xv = x2s[cur][pair] + half * 18;
        const ull* hv = h2s[cur][pair] + half * 10;
#pragma unroll
        for (int f = 0; f < 18; ++f) {
            ull v = xv[f];
            ar = fma2(wih[0][f], v, ar);
            az = fma2(wih[1][f], v, az);
            ain = fma2(wih[2][f], v, ain);
        }
#pragma unroll
        for (int j = 0; j < 10; ++j) {
            ull v = hv[j];
            ar = fma2(whh_sh[0][j][l], v, ar);
            az = fma2(whh_sh[1][j][l], v, az);
            ahn = fma2(whh_sh[2][j][l], v, ahn);
        }
        ar = add2(ar, __shfl_xor_sync(0xffffffffu, ar, 1));
        az = add2(az, __shfl_xor_sync(0xffffffffu, az, 1));
        ain = add2(ain, __shfl_xor_sync(0xffffffffu, ain, 1));
        ahn = add2(ahn, __shfl_xor_sync(0xffffffffu, ahn, 1));

        float rl, rh, zl, zh, il, ih, nl, nh;
        upk2(ar, rl, rh); upk2(az, zl, zh); upk2(ain, il, ih); upk2(ahn, nl, nh);
        float r0 = sigm_fast(rl + br), r1 = sigm_fast(rh + br);
        float z0 = sigm_fast(zl + bz), z1 = sigm_fast(zh + bz);
        float n0 = tanh_fast(il + bin_ + r0 * (nl + bhn));
        float n1 = tanh_fast(ih + bin_ + r1 * (nh + bhn));
        hlo = tanh_fast(fmaf(z0, hlo - n0, n0));
        hhi = tanh_fast(fmaf(z1, hhi - n1, n1));

        if (half == 0) h2s[nxt][pair][k] = pk2(hlo, hhi);
        __syncthreads();

        // xnew = tanh(hnew @ Wfc^T + bfc), write flipped
        if (l < FF) {
            ull acc = bfc2;
#pragma unroll
            for (int j = 0; j < HH; ++j)
                acc = fma2(wfc_pk[j], h2s[nxt][pair][j], acc);
            float xa, xb;
            upk2(acc, xa, xb);
            xa = tanh_fast(xa);
            xb = tanh_fast(xb);
            int so = SS - 1 - st;
            orow0[(size_t)so * FF + l] = xa;
            orow1[(size_t)so * FF + l] = xb;
            x2s[nxt][pair][l] = pk2(xa, xb);
        }
        __syncthreads();
        cur = nxt;
    }
}

// ---------------------------------------------------------------------------
// Launch
// ---------------------------------------------------------------------------
extern "C" void kernel_launch(void* const* d_in, const int* in_sizes, int n_in,
                              void* d_out, int out_size) {
    const float* x = (const float*)d_in[0];
    const int* oh = (const int*)d_in[1];
    const float* e0 = (const float*)d_in[2];
    const float* e1 = (const float*)d_in[3];
    const float* e2 = (const float*)d_in[4];
    const float* e3 = (const float*)d_in[5];
    const float* Wih1 = (const float*)d_in[6];
    const float* Whh1 = (const float*)d_in[7];
    const float* bih1 = (const float*)d_in[8];
    const float* bhh1 = (const float*)d_in[9];
    const float* Wih2 = (const float*)d_in[10];
    const float* Whh2 = (const float*)d_in[11];
    const float* bih2 = (const float*)d_in[12];
    const float* bhh2 = (const float*)d_in[13];
    const float* Wfc = (const float*)d_in[14];
    const float* bfc = (const float*)d_in[15];

    float* out = (float*)d_out;
    float* origin = out;                          // (B,S,F)
    float* xs = out + (size_t)BB * SS * FF;       // (B,S,F) flipped decode

    detect_kernel<<<1, 32>>>(oh);
    embed_kernel<<<(BB * SS + 255) / 256, 256>>>(x, oh, e0, e1, e2, e3, origin);
    encoder_kernel<<<BB / 8, 160>>>(origin, Wih1, Whh1, bih1, bhh1);
    decoder_kernel<<<BB / 8, 160>>>(Wih2, Whh2, bih2, bhh2, Wfc, bfc, xs);
}

// round 6
// speedup vs baseline: 1.3059x; 1.2385x over previous
#include <cuda_runtime.h>
#include <cstdint>
#include <cstddef>

#define BB 1024
#define SS 1024
#define FF 36
#define HH 20
#define FULLMASK 0xffffffffu

typedef unsigned long long ull;

// Scratch: encoder final hidden state (tanh'd), packed per batch-pair.
__device__ ull g_h2[(BB / 2) * HH];
__device__ int g_oh64;

// ---------------------------------------------------------------------------
// f32x2 packed helpers
// ---------------------------------------------------------------------------
__device__ __forceinline__ ull pk2(float a, float b) {
    ull r; asm("mov.b64 %0,{%1,%2};" : "=l"(r) : "f"(a), "f"(b)); return r;
}
__device__ __forceinline__ void upk2(ull v, float& a, float& b) {
    asm("mov.b64 {%0,%1},%2;" : "=f"(a), "=f"(b) : "l"(v));
}
__device__ __forceinline__ ull fma2(ull a, ull b, ull c) {
    ull d; asm("fma.rn.f32x2 %0,%1,%2,%3;" : "=l"(d) : "l"(a), "l"(b), "l"(c)); return d;
}
__device__ __forceinline__ ull add2(ull a, ull b) {
    ull d; asm("add.rn.f32x2 %0,%1,%2;" : "=l"(d) : "l"(a), "l"(b)); return d;
}

// ---------------------------------------------------------------------------
// HW tanh (MUFU.TANH, sm_75+). 1 MUFU op; abs err ~1e-5.
// ---------------------------------------------------------------------------
__device__ __forceinline__ float tanh_hw(float x) {
    float y; asm("tanh.approx.f32 %0,%1;" : "=f"(y) : "f"(x)); return y;
}
__device__ __forceinline__ float sigm_hw(float v) {
    return fmaf(0.5f, tanh_hw(0.5f * v), 0.5f);
}

// ---------------------------------------------------------------------------
// Detect int64 vs int32 onehots.
// ---------------------------------------------------------------------------
__global__ void detect_kernel(const int* __restrict__ oh) {
    if (threadIdx.x == 0 && blockIdx.x == 0) {
        int z = 1;
        for (int i = 1; i < 64; i += 2)
            if (oh[i] != 0) { z = 0; break; }
        g_oh64 = z;
    }
}

// ---------------------------------------------------------------------------
// Embedding + concat -> origin.
// ---------------------------------------------------------------------------
__global__ void embed_kernel(const float* __restrict__ x,
                             const int* __restrict__ oh,
                             const float* __restrict__ e0,
                             const float* __restrict__ e1,
                             const float* __restrict__ e2,
                             const float* __restrict__ e3,
                             float* __restrict__ origin) {
    int idx = blockIdx.x * blockDim.x + threadIdx.x;
    if (idx >= BB * SS) return;
    int i0, i1, i2, i3;
    if (g_oh64) {
        const int* p = oh + (size_t)idx * 8;
        i0 = p[0]; i1 = p[2]; i2 = p[4]; i3 = p[6];
    } else {
        int4 o = reinterpret_cast<const int4*>(oh)[idx];
        i0 = o.x; i1 = o.y; i2 = o.z; i3 = o.w;
    }
    const float4* xr = reinterpret_cast<const float4*>(x + (size_t)idx * 12);
    float4* out = reinterpret_cast<float4*>(origin + (size_t)idx * FF);
    out[0] = xr[0];
    out[1] = xr[1];
    out[2] = xr[2];
    out[3] = reinterpret_cast<const float4*>(e0)[i0];
    out[4] = reinterpret_cast<const float4*>(e1)[i1];
    const float4* e2p = reinterpret_cast<const float4*>(e2);
    out[5] = e2p[i2 * 2];
    out[6] = e2p[i2 * 2 + 1];
    const float4* e3p = reinterpret_cast<const float4*>(e3);
    out[7] = e3p[i3 * 2];
    out[8] = e3p[i3 * 2 + 1];
}

// ---------------------------------------------------------------------------
// Gate-lane decomposition shared by encoder/decoder:
// CTA = 128 threads = 1 batch-pair. warp w (0..3), lane lw (0..31).
// lw = u*6 + g*2 + half for u<5 (2 idle lanes/warp). unit k = w*5+u.
// Thread computes half the dot of one gate; 6 shfls combine/gather.
// ---------------------------------------------------------------------------

__global__ void __launch_bounds__(128, 4) encoder_kernel(
    const float* __restrict__ xin,
    const float* __restrict__ Wih, const float* __restrict__ Whh,
    const float* __restrict__ bih, const float* __restrict__ bhh) {
    __shared__ __align__(16) ull x2s[2][FF];
    __shared__ __align__(16) ull h2s[2][HH];

    int tid = threadIdx.x;
    int w = tid >> 5, lw = tid & 31;
    int u = lw / 6, rem = lw % 6;
    bool valid = (u < 5);
    int k = valid ? (w * 5 + u) : 0;
    int g = rem >> 1, half = rem & 1;
    int base = (lw / 6) * 6;
    int gp = blockIdx.x;
    int b0 = gp * 2, b1 = b0 + 1;

    int row = g * HH + k;
    ull wx[18], wh[10];
#pragma unroll
    for (int f = 0; f < 18; f++) { float v = Wih[row * FF + half * 18 + f]; wx[f] = pk2(v, v); }
#pragma unroll
    for (int j = 0; j < 10; j++) { float v = Whh[row * HH + half * 10 + j]; wh[j] = pk2(v, v); }
    float br = bih[k] + bhh[k];
    float bz = bih[HH + k] + bhh[HH + k];
    float bi = bih[2 * HH + k];
    float bh = bhh[2 * HH + k];

    const float* xr0 = xin + (size_t)b0 * SS * FF;
    const float* xr1 = xin + (size_t)b1 * SS * FF;

    float pa = 0.f, pb = 0.f;
    if (tid < FF) {
        x2s[0][tid] = pk2(xr0[tid], xr1[tid]);
        pa = xr0[FF + tid]; pb = xr1[FF + tid];
    }
    if (tid < HH) h2s[0][tid] = 0ULL;
    __syncthreads();

    float h0 = 0.f, h1 = 0.f;

    for (int s = 0; s < SS; ++s) {
        int cur = s & 1, nxt = cur ^ 1;
        if (tid < FF) {
            if (s + 1 < SS) x2s[nxt][tid] = pk2(pa, pb);
            if (s + 2 < SS) {
                pa = xr0[(size_t)(s + 2) * FF + tid];
                pb = xr1[(size_t)(s + 2) * FF + tid];
            }
        }
        ull ax = 0, ah = 0;
        const ulonglong2* xv = reinterpret_cast<const ulonglong2*>(&x2s[cur][half * 18]);
#pragma unroll
        for (int i = 0; i < 9; i++) {
            ulonglong2 v = xv[i];
            ax = fma2(wx[2 * i], v.x, ax);
            ax = fma2(wx[2 * i + 1], v.y, ax);
        }
        const ulonglong2* hv = reinterpret_cast<const ulonglong2*>(&h2s[cur][half * 10]);
#pragma unroll
        for (int i = 0; i < 5; i++) {
            ulonglong2 v = hv[i];
            ah = fma2(wh[2 * i], v.x, ah);
            ah = fma2(wh[2 * i + 1], v.y, ah);
        }
        ull accA = (g == 2) ? ax : add2(ax, ah);
        ull accB = ah;
        accA = add2(accA, __shfl_xor_sync(FULLMASK, accA, 1));
        accB = add2(accB, __shfl_xor_sync(FULLMASK, accB, 1));
        ull R = __shfl_sync(FULLMASK, accA, base);
        ull Z = __shfl_sync(FULLMASK, accA, base + 2);
        ull IN = __shfl_sync(FULLMASK, accA, base + 4);
        ull HN = __shfl_sync(FULLMASK, accB, base + 4);
        float Rl, Rh, Zl, Zh, Il, Ih, Nl, Nh;
        upk2(R, Rl, Rh); upk2(Z, Zl, Zh); upk2(IN, Il, Ih); upk2(HN, Nl, Nh);
        float r0 = sigm_hw(Rl + br), r1 = sigm_hw(Rh + br);
        float z0 = sigm_hw(Zl + bz), z1 = sigm_hw(Zh + bz);
        float n0 = tanh_hw(Il + bi + r0 * (Nl + bh));
        float n1 = tanh_hw(Ih + bi + r1 * (Nh + bh));
        h0 = fmaf(z0, h0 - n0, n0);
        h1 = fmaf(z1, h1 - n1, n1);
        if (valid && rem == 0) h2s[nxt][k] = pk2(h0, h1);
        __syncthreads();
    }
    if (valid && rem == 0)
        g_h2[gp * HH + k] = pk2(tanh_hw(h0), tanh_hw(h1));
}

// ---------------------------------------------------------------------------
// Decoder: phase 1 = tanh-GRU gates (same decomposition); phase 2 = Wfc
// projection split 2-way over 72 lanes (o = lane>>1, half = lane&1).
// ---------------------------------------------------------------------------
__global__ void __launch_bounds__(128, 4) decoder_kernel(
    const float* __restrict__ Wih, const float* __restrict__ Whh,
    const float* __restrict__ bih, const float* __restrict__ bhh,
    const float* __restrict__ Wfc, const float* __restrict__ bfc,
    float* __restrict__ out_xs) {
    __shared__ __align__(16) ull x2s[2][FF];
    __shared__ __align__(16) ull h2s[2][HH];
    __shared__ ull wfc_sh[72 * 11];

    int tid = threadIdx.x;
    int w = tid >> 5, lw = tid & 31;
    int u = lw / 6, rem = lw % 6;
    bool valid = (u < 5);
    int k = valid ? (w * 5 + u) : 0;
    int g = rem >> 1, half = rem & 1;
    int base = (lw / 6) * 6;
    int gp = blockIdx.x;
    int b0 = gp * 2, b1 = b0 + 1;

    int row = g * HH + k;
    ull wx[18], wh[10];
#pragma unroll
    for (int f = 0; f < 18; f++) { float v = Wih[row * FF + half * 18 + f]; wx[f] = pk2(v, v); }
#pragma unroll
    for (int j = 0; j < 10; j++) { float v = Whh[row * HH + half * 10 + j]; wh[j] = pk2(v, v); }
    float br = bih[k] + bhh[k];
    float bz = bih[HH + k] + bhh[HH + k];
    float bi = bih[2 * HH + k];
    float bh = bhh[2 * HH + k];

    // Projection role: lanes 0..71, o = feature, hf = K-half of the 20-dot
    int o = tid >> 1, hf = tid & 1;
    bool pvalid = (tid < 72);
    float bo = pvalid ? bfc[o] : 0.f;

    for (int i = tid; i < 720; i += 128) {
        int pl = i / 10, j = i % 10;
        int oo = pl >> 1, hh = pl & 1;
        float v = Wfc[oo * HH + hh * 10 + j];
        wfc_sh[pl * 11 + j] = pk2(v, v);
    }

    ull hp = g_h2[gp * HH + k];
    float h0, h1;
    upk2(hp, h0, h1);
    if (tid < HH) h2s[0][tid] = g_h2[gp * HH + tid];
    __syncthreads();

    float* orow0 = out_xs + (size_t)b0 * SS * FF;
    float* orow1 = out_xs + (size_t)b1 * SS * FF;

    // x0 projection from h2s[0] -> x2s[0], flipped position SS-1
    {
        ull acc = 0;
        if (pvalid) {
            const ulonglong2* hv = reinterpret_cast<const ulonglong2*>(&h2s[0][hf * 10]);
#pragma unroll
            for (int i = 0; i < 5; i++) {
                ulonglong2 v = hv[i];
                acc = fma2(wfc_sh[tid * 11 + 2 * i], v.x, acc);
                acc = fma2(wfc_sh[tid * 11 + 2 * i + 1], v.y, acc);
            }
        }
        acc = add2(acc, __shfl_xor_sync(FULLMASK, acc, 1));
        if (pvalid && hf == 0) {
            float lo, hi; upk2(acc, lo, hi);
            float xa = tanh_hw(lo + bo), xb = tanh_hw(hi + bo);
            orow0[(size_t)(SS - 1) * FF + o] = xa;
            orow1[(size_t)(SS - 1) * FF + o] = xb;
            x2s[0][o] = pk2(xa, xb);
        }
    }
    __syncthreads();

    int cur = 0;
    for (int st = 1; st < SS; ++st) {
        int nxt = cur ^ 1;
        // phase 1: gates
        ull ax = 0, ah = 0;
        const ulonglong2* xv = reinterpret_cast<const ulonglong2*>(&x2s[cur][half * 18]);
#pragma unroll
        for (int i = 0; i < 9; i++) {
            ulonglong2 v = xv[i];
            ax = fma2(wx[2 * i], v.x, ax);
            ax = fma2(wx[2 * i + 1], v.y, ax);
        }
        const ulonglong2* hv = reinterpret_cast<const ulonglong2*>(&h2s[cur][half * 10]);
#pragma unroll
        for (int i = 0; i < 5; i++) {
            ulonglong2 v = hv[i];
            ah = fma2(wh[2 * i], v.x, ah);
            ah = fma2(wh[2 * i + 1], v.y, ah);
        }
        ull accA = (g == 2) ? ax : add2(ax, ah);
        ull accB = ah;
        accA = add2(accA, __shfl_xor_sync(FULLMASK, accA, 1));
        accB = add2(accB, __shfl_xor_sync(FULLMASK, accB, 1));
        ull R = __shfl_sync(FULLMASK, accA, base);
        ull Z = __shfl_sync(FULLMASK, accA, base + 2);
        ull IN = __shfl_sync(FULLMASK, accA, base + 4);
        ull HN = __shfl_sync(FULLMASK, accB, base + 4);
        float Rl, Rh, Zl, Zh, Il, Ih, Nl, Nh;
        upk2(R, Rl, Rh); upk2(Z, Zl, Zh); upk2(IN, Il, Ih); upk2(HN, Nl, Nh);
        float r0 = sigm_hw(Rl + br), r1 = sigm_hw(Rh + br);
        float z0 = sigm_hw(Zl + bz), z1 = sigm_hw(Zh + bz);
        float n0 = tanh_hw(Il + bi + r0 * (Nl + bh));
        float n1 = tanh_hw(Ih + bi + r1 * (Nh + bh));
        h0 = tanh_hw(fmaf(z0, h0 - n0, n0));
        h1 = tanh_hw(fmaf(z1, h1 - n1, n1));
        if (valid && rem == 0) h2s[nxt][k] = pk2(h0, h1);
        __syncthreads();

        // phase 2: projection from h2s[nxt] -> x2s[nxt] + global (flipped)
        ull acc = 0;
        if (pvalid) {
            const ulonglong2* hv2 = reinterpret_cast<const ulonglong2*>(&h2s[nxt][hf * 10]);
#pragma unroll
            for (int i = 0; i < 5; i++) {
                ulonglong2 v = hv2[i];
                acc = fma2(wfc_sh[tid * 11 + 2 * i], v.x, acc);
                acc = fma2(wfc_sh[tid * 11 + 2 * i + 1], v.y, acc);
            }
        }
        acc = add2(acc, __shfl_xor_sync(FULLMASK, acc, 1));
        if (pvalid && hf == 0) {
            float lo, hi; upk2(acc, lo, hi);
            float xa = tanh_hw(lo + bo), xb = tanh_hw(hi + bo);
            int so = SS - 1 - st;
            orow0[(size_t)so * FF + o] = xa;
            orow1[(size_t)so * FF + o] = xb;
            x2s[nxt][o] = pk2(xa, xb);
        }
        __syncthreads();
        cur = nxt;
    }
}

// ---------------------------------------------------------------------------
// Launch
// ---------------------------------------------------------------------------
extern "C" void kernel_launch(void* const* d_in, const int* in_sizes, int n_in,
                              void* d_out, int out_size) {
    const float* x = (const float*)d_in[0];
    const int* oh = (const int*)d_in[1];
    const float* e0 = (const float*)d_in[2];
    const float* e1 = (const float*)d_in[3];
    const float* e2 = (const float*)d_in[4];
    const float* e3 = (const float*)d_in[5];
    const float* Wih1 = (const float*)d_in[6];
    const float* Whh1 = (const float*)d_in[7];
    const float* bih1 = (const float*)d_in[8];
    const float* bhh1 = (const float*)d_in[9];
    const float* Wih2 = (const float*)d_in[10];
    const float* Whh2 = (const float*)d_in[11];
    const float* bih2 = (const float*)d_in[12];
    const float* bhh2 = (const float*)d_in[13];
    const float* Wfc = (const float*)d_in[14];
    const float* bfc = (const float*)d_in[15];

    float* out = (float*)d_out;
    float* origin = out;                          // (B,S,F)
    float* xs = out + (size_t)BB * SS * FF;       // (B,S,F) flipped decode

    detect_kernel<<<1, 32>>>(oh);
    embed_kernel<<<(BB * SS + 255) / 256, 256>>>(x, oh, e0, e1, e2, e3, origin);
    encoder_kernel<<<BB / 2, 128>>>(origin, Wih1, Whh1, bih1, bhh1);
    decoder_kernel<<<BB / 2, 128>>>(Wih2, Whh2, bih2, bhh2, Wfc, bfc, xs);
}

// round 7
// speedup vs baseline: 1.5884x; 1.2163x over previous
#include <cuda_runtime.h>
#include <cstdint>
#include <cstddef>

#define BB 1024
#define SS 1024
#define FF 36
#define HH 20
#define FULLMASK 0xffffffffu

typedef unsigned long long ull;

// Scratch: encoder final hidden state (tanh'd), packed per batch-pair.
__device__ ull g_h2[(BB / 2) * HH];
__device__ int g_oh64;

// ---------------------------------------------------------------------------
// f32x2 packed helpers
// ---------------------------------------------------------------------------
__device__ __forceinline__ ull pk2(float a, float b) {
    ull r; asm("mov.b64 %0,{%1,%2};" : "=l"(r) : "f"(a), "f"(b)); return r;
}
__device__ __forceinline__ void upk2(ull v, float& a, float& b) {
    asm("mov.b64 {%0,%1},%2;" : "=f"(a), "=f"(b) : "l"(v));
}
__device__ __forceinline__ ull fma2(ull a, ull b, ull c) {
    ull d; asm("fma.rn.f32x2 %0,%1,%2,%3;" : "=l"(d) : "l"(a), "l"(b), "l"(c)); return d;
}
__device__ __forceinline__ ull add2(ull a, ull b) {
    ull d; asm("add.rn.f32x2 %0,%1,%2;" : "=l"(d) : "l"(a), "l"(b)); return d;
}

// ---------------------------------------------------------------------------
// HW tanh (MUFU.TANH). 1 MUFU op; abs err ~1e-5.
// ---------------------------------------------------------------------------
__device__ __forceinline__ float tanh_hw(float x) {
    float y; asm("tanh.approx.f32 %0,%1;" : "=f"(y) : "f"(x)); return y;
}
__device__ __forceinline__ float sigm_hw(float v) {
    return fmaf(0.5f, tanh_hw(0.5f * v), 0.5f);
}

// ---------------------------------------------------------------------------
// Detect int64 vs int32 onehots.
// ---------------------------------------------------------------------------
__global__ void detect_kernel(const int* __restrict__ oh) {
    if (threadIdx.x == 0 && blockIdx.x == 0) {
        int z = 1;
        for (int i = 1; i < 64; i += 2)
            if (oh[i] != 0) { z = 0; break; }
        g_oh64 = z;
    }
}

// ---------------------------------------------------------------------------
// Embedding + concat -> origin.
// ---------------------------------------------------------------------------
__global__ void embed_kernel(const float* __restrict__ x,
                             const int* __restrict__ oh,
                             const float* __restrict__ e0,
                             const float* __restrict__ e1,
                             const float* __restrict__ e2,
                             const float* __restrict__ e3,
                             float* __restrict__ origin) {
    int idx = blockIdx.x * blockDim.x + threadIdx.x;
    if (idx >= BB * SS) return;
    int i0, i1, i2, i3;
    if (g_oh64) {
        const int* p = oh + (size_t)idx * 8;
        i0 = p[0]; i1 = p[2]; i2 = p[4]; i3 = p[6];
    } else {
        int4 o = reinterpret_cast<const int4*>(oh)[idx];
        i0 = o.x; i1 = o.y; i2 = o.z; i3 = o.w;
    }
    const float4* xr = reinterpret_cast<const float4*>(x + (size_t)idx * 12);
    float4* out = reinterpret_cast<float4*>(origin + (size_t)idx * FF);
    out[0] = xr[0];
    out[1] = xr[1];
    out[2] = xr[2];
    out[3] = reinterpret_cast<const float4*>(e0)[i0];
    out[4] = reinterpret_cast<const float4*>(e1)[i1];
    const float4* e2p = reinterpret_cast<const float4*>(e2);
    out[5] = e2p[i2 * 2];
    out[6] = e2p[i2 * 2 + 1];
    const float4* e3p = reinterpret_cast<const float4*>(e3);
    out[7] = e3p[i3 * 2];
    out[8] = e3p[i3 * 2 + 1];
}

// ---------------------------------------------------------------------------
// Gate-only decomposition: CTA = 64 threads = 1 batch-pair, 2 warps.
// warp w owns units w*10..w*10+9; lane lw = u*3 + g (u<10, 2 idle lanes).
// Each lane computes the FULL packed 56-dot for one gate (no K split):
// 56 fma2, 28 LDS.128, zero reduce-shfls; 4 idx-shfls gather gate sums.
// ---------------------------------------------------------------------------

struct GateCtx {
    ull wx[FF];
    ull wh[HH];
    float br, bz, bi, bh;
    int bl;       // base lane (within warp) of this thread's unit
    bool lead;    // g==0 && active: writes h
    int k;
};

__device__ __forceinline__ void load_gate_ctx(
    GateCtx& C, int tid,
    const float* __restrict__ Wih, const float* __restrict__ Whh,
    const float* __restrict__ bih, const float* __restrict__ bhh) {
    int w = tid >> 5, lw = tid & 31;
    int u = lw / 3;
    bool act = (u < 10);
    int uc = act ? u : 9;
    int g = lw - u * 3;
    C.k = w * 10 + uc;
    C.bl = uc * 3;
    C.lead = act && (g == 0);
    int row = g * HH + C.k;
#pragma unroll
    for (int f = 0; f < FF; f++) { float v = Wih[row * FF + f]; C.wx[f] = pk2(v, v); }
#pragma unroll
    for (int j = 0; j < HH; j++) { float v = Whh[row * HH + j]; C.wh[j] = pk2(v, v); }
    C.br = bih[C.k] + bhh[C.k];
    C.bz = bih[HH + C.k] + bhh[HH + C.k];
    C.bi = bih[2 * HH + C.k];
    C.bh = bhh[2 * HH + C.k];
}

// Compute one GRU cell for the packed pair; returns new h (not stored).
__device__ __forceinline__ void gru_gates(
    const GateCtx& C, const ull* __restrict__ xc, const ull* __restrict__ hc,
    float& h0, float& h1) {
    ull ax0 = 0, ax1 = 0, ah0 = 0, ah1 = 0;
    const ulonglong2* xv = reinterpret_cast<const ulonglong2*>(xc);
#pragma unroll
    for (int i = 0; i < 18; i++) {
        ulonglong2 v = xv[i];
        ax0 = fma2(C.wx[2 * i], v.x, ax0);
        ax1 = fma2(C.wx[2 * i + 1], v.y, ax1);
    }
    const ulonglong2* hv = reinterpret_cast<const ulonglong2*>(hc);
#pragma unroll
    for (int i = 0; i < 10; i++) {
        ulonglong2 v = hv[i];
        ah0 = fma2(C.wh[2 * i], v.x, ah0);
        ah1 = fma2(C.wh[2 * i + 1], v.y, ah1);
    }
    ull ax = add2(ax0, ax1);
    ull ah = add2(ah0, ah1);
    int lw = threadIdx.x & 31;
    int g = lw - (lw / 3) * 3;
    ull accA = (g == 2) ? ax : add2(ax, ah);
    ull accB = ah;
    ull R = __shfl_sync(FULLMASK, accA, C.bl);
    ull Z = __shfl_sync(FULLMASK, accA, C.bl + 1);
    ull IN = __shfl_sync(FULLMASK, accA, C.bl + 2);
    ull HN = __shfl_sync(FULLMASK, accB, C.bl + 2);
    float Rl, Rh, Zl, Zh, Il, Ih, Nl, Nh;
    upk2(R, Rl, Rh); upk2(Z, Zl, Zh); upk2(IN, Il, Ih); upk2(HN, Nl, Nh);
    float r0 = sigm_hw(Rl + C.br), r1 = sigm_hw(Rh + C.br);
    float z0 = sigm_hw(Zl + C.bz), z1 = sigm_hw(Zh + C.bz);
    float n0 = tanh_hw(Il + C.bi + r0 * (Nl + C.bh));
    float n1 = tanh_hw(Ih + C.bi + r1 * (Nh + C.bh));
    h0 = fmaf(z0, h0 - n0, n0);
    h1 = fmaf(z1, h1 - n1, n1);
}

// ---------------------------------------------------------------------------
// Encoder
// ---------------------------------------------------------------------------
__global__ void __launch_bounds__(64, 4) encoder_kernel(
    const float* __restrict__ xin,
    const float* __restrict__ Wih, const float* __restrict__ Whh,
    const float* __restrict__ bih, const float* __restrict__ bhh) {
    __shared__ __align__(16) ull x2s[2][FF];
    __shared__ __align__(16) ull h2s[2][HH];

    int tid = threadIdx.x;
    GateCtx C;
    load_gate_ctx(C, tid, Wih, Whh, bih, bhh);

    int gp = blockIdx.x;
    const float* xr0 = xin + (size_t)(gp * 2) * SS * FF;
    const float* xr1 = xin + (size_t)(gp * 2 + 1) * SS * FF;

    float pa = 0.f, pb = 0.f;
    if (tid < FF) {
        x2s[0][tid] = pk2(xr0[tid], xr1[tid]);
        pa = xr0[FF + tid]; pb = xr1[FF + tid];
    }
    if (tid < HH) h2s[0][tid] = 0ULL;
    __syncthreads();

    float h0 = 0.f, h1 = 0.f;

    auto step = [&](int s, const ull* xc, const ull* hc, ull* xn, ull* hn) {
        if (tid < FF) {
            if (s + 1 < SS) xn[tid] = pk2(pa, pb);
            if (s + 2 < SS) {
                pa = xr0[(size_t)(s + 2) * FF + tid];
                pb = xr1[(size_t)(s + 2) * FF + tid];
            }
        }
        gru_gates(C, xc, hc, h0, h1);
        if (C.lead) hn[C.k] = pk2(h0, h1);
        __syncthreads();
    };

    for (int s = 0; s < SS; s += 2) {
        step(s, x2s[0], h2s[0], x2s[1], h2s[1]);
        step(s + 1, x2s[1], h2s[1], x2s[0], h2s[0]);
    }

    if (C.lead)
        g_h2[gp * HH + C.k] = pk2(tanh_hw(h0), tanh_hw(h1));
}

// ---------------------------------------------------------------------------
// Decoder: phase 1 = tanh-GRU gates; phase 2 = Wfc projection with the full
// Wfc row held in per-lane registers (lane o = tid < 36), no shared Wfc.
// ---------------------------------------------------------------------------
__global__ void __launch_bounds__(64, 4) decoder_kernel(
    const float* __restrict__ Wih, const float* __restrict__ Whh,
    const float* __restrict__ bih, const float* __restrict__ bhh,
    const float* __restrict__ Wfc, const float* __restrict__ bfc,
    float* __restrict__ out_xs) {
    __shared__ __align__(16) ull x2s[2][FF];
    __shared__ __align__(16) ull h2s[2][HH];

    int tid = threadIdx.x;
    GateCtx C;
    load_gate_ctx(C, tid, Wih, Whh, bih, bhh);

    // Projection context: lane o = tid (o < 36) owns output feature o.
    bool pv = (tid < FF);
    int o = pv ? tid : 0;
    ull wfcp[HH];
#pragma unroll
    for (int j = 0; j < HH; j++) { float v = Wfc[o * HH + j]; wfcp[j] = pk2(v, v); }
    float bo = bfc[o];

    int gp = blockIdx.x;
    float* orow0 = out_xs + (size_t)(gp * 2) * SS * FF;
    float* orow1 = out_xs + (size_t)(gp * 2 + 1) * SS * FF;

    ull hp = g_h2[gp * HH + C.k];
    float h0, h1;
    upk2(hp, h0, h1);
    if (tid < HH) h2s[0][tid] = g_h2[gp * HH + tid];
    __syncthreads();

    auto proj = [&](const ull* hsrc, ull* xdst, int so) {
        ull a0 = 0, a1 = 0;
        const ulonglong2* hv = reinterpret_cast<const ulonglong2*>(hsrc);
#pragma unroll
        for (int i = 0; i < 10; i++) {
            ulonglong2 v = hv[i];
            a0 = fma2(wfcp[2 * i], v.x, a0);
            a1 = fma2(wfcp[2 * i + 1], v.y, a1);
        }
        ull acc = add2(a0, a1);
        if (pv) {
            float lo, hi; upk2(acc, lo, hi);
            float xa = tanh_hw(lo + bo), xb = tanh_hw(hi + bo);
            orow0[(size_t)so * FF + o] = xa;
            orow1[(size_t)so * FF + o] = xb;
            xdst[o] = pk2(xa, xb);
        }
        __syncthreads();
    };

    // x0 from h2s[0] -> x2s[0], flipped position SS-1
    proj(h2s[0], x2s[0], SS - 1);

    auto dstep = [&](int st, const ull* xc, const ull* hc, ull* xn, ull* hn) {
        gru_gates(C, xc, hc, h0, h1);
        h0 = tanh_hw(h0);
        h1 = tanh_hw(h1);
        if (C.lead) hn[C.k] = pk2(h0, h1);
        __syncthreads();
        proj(hn, xn, SS - 1 - st);
    };

    for (int st = 1; st < SS; st += 2) {
        dstep(st, x2s[0], h2s[0], x2s[1], h2s[1]);
        if (st + 1 < SS)
            dstep(st + 1, x2s[1], h2s[1], x2s[0], h2s[0]);
    }
}

// ---------------------------------------------------------------------------
// Launch
// ---------------------------------------------------------------------------
extern "C" void kernel_launch(void* const* d_in, const int* in_sizes, int n_in,
                              void* d_out, int out_size) {
    const float* x = (const float*)d_in[0];
    const int* oh = (const int*)d_in[1];
    const float* e0 = (const float*)d_in[2];
    const float* e1 = (const float*)d_in[3];
    const float* e2 = (const float*)d_in[4];
    const float* e3 = (const float*)d_in[5];
    const float* Wih1 = (const float*)d_in[6];
    const float* Whh1 = (const float*)d_in[7];
    const float* bih1 = (const float*)d_in[8];
    const float* bhh1 = (const float*)d_in[9];
    const float* Wih2 = (const float*)d_in[10];
    const float* Whh2 = (const float*)d_in[11];
    const float* bih2 = (const float*)d_in[12];
    const float* bhh2 = (const float*)d_in[13];
    const float* Wfc = (const float*)d_in[14];
    const float* bfc = (const float*)d_in[15];

    float* out = (float*)d_out;
    float* origin = out;                          // (B,S,F)
    float* xs = out + (size_t)BB * SS * FF;       // (B,S,F) flipped decode

    detect_kernel<<<1, 32>>>(oh);
    embed_kernel<<<(BB * SS + 255) / 256, 256>>>(x, oh, e0, e1, e2, e3, origin);
    encoder_kernel<<<BB / 2, 64>>>(origin, Wih1, Whh1, bih1, bhh1);
    decoder_kernel<<<BB / 2, 64>>>(Wih2, Whh2, bih2, bhh2, Wfc, bfc, xs);
}